// round 4
// baseline (speedup 1.0000x reference)
#include <cuda_runtime.h>
#include <cuda_fp16.h>
#include <cstdint>

// CoarseMatching: N=2, L=S=4800, C=256
#define NB 2
#define LL 4800
#define SS 4800
#define CC 256
#define TILE 128
#define NT ((LL + TILE - 1) / TILE)   // 38
#define LPAD (NT * TILE)              // 4864 padded rows
#define BK 32
#define NK (CC / BK)                  // 8
#define PAD 40                        // smem row stride in halves (80B)
#define SIMSC 0.0390625f              // (1/256)/0.1
#define THRV 0.2f

// ---------------- device scratch ----------------
__device__ __half g_h0[NB * LPAD * CC];
__device__ __half g_h1[NB * LPAD * CC];
__device__ float  g_R [NB * LL];   // row sums of exp(sim)
__device__ float  g_Cs[NB * SS];   // col sums of exp(sim)
__device__ float  g_iR[NB * LL];   // reciprocals
__device__ float  g_iC[NB * SS];
__device__ float  g_RM[NB * LL];   // per-row max of conf

// ---------------- PTX helpers ----------------
__device__ __forceinline__ uint32_t sm2u(const void* p) {
    uint32_t a;
    asm("{ .reg .u64 t; cvta.to.shared.u64 t, %1; cvt.u32.u64 %0, t; }" : "=r"(a) : "l"(p));
    return a;
}

__device__ __forceinline__ void ldsm4(uint32_t* r, uint32_t addr) {
    asm volatile("ldmatrix.sync.aligned.m8n8.x4.shared.b16 {%0,%1,%2,%3}, [%4];"
                 : "=r"(r[0]), "=r"(r[1]), "=r"(r[2]), "=r"(r[3]) : "r"(addr));
}

__device__ __forceinline__ void mma16816(float* d, const uint32_t* a, uint32_t b0, uint32_t b1) {
    asm volatile(
        "mma.sync.aligned.m16n8k16.row.col.f32.f16.f16.f32 "
        "{%0,%1,%2,%3}, {%4,%5,%6,%7}, {%8,%9}, {%0,%1,%2,%3};"
        : "+f"(d[0]), "+f"(d[1]), "+f"(d[2]), "+f"(d[3])
        : "r"(a[0]), "r"(a[1]), "r"(a[2]), "r"(a[3]), "r"(b0), "r"(b1));
}

// ---------------- prep: fp32 -> fp16 with zero padding ----------------
__global__ void prep_kernel(const float* __restrict__ f0, const float* __restrict__ f1) {
    long long i = (long long)blockIdx.x * blockDim.x + threadIdx.x;   // one uint2 (4 halves)
    long long n4 = (long long)NB * LPAD * CC / 4;
    if (i >= n4) return;
    long long t = i * 4;
    int nb = (int)(t / ((long long)LPAD * CC));
    long long rem = t % ((long long)LPAD * CC);
    int row = (int)(rem / CC), c = (int)(rem % CC);
    uint2 z0 = make_uint2(0u, 0u), z1 = make_uint2(0u, 0u);
    if (row < LL) {
        long long s = ((long long)nb * LL + row) * CC + c;
        float4 a = *reinterpret_cast<const float4*>(f0 + s);
        float4 b = *reinterpret_cast<const float4*>(f1 + s);
        __half2 a01 = __floats2half2_rn(a.x, a.y), a23 = __floats2half2_rn(a.z, a.w);
        __half2 b01 = __floats2half2_rn(b.x, b.y), b23 = __floats2half2_rn(b.z, b.w);
        z0 = make_uint2(*(uint32_t*)&a01, *(uint32_t*)&a23);
        z1 = make_uint2(*(uint32_t*)&b01, *(uint32_t*)&b23);
    }
    reinterpret_cast<uint2*>(g_h0)[i] = z0;
    reinterpret_cast<uint2*>(g_h1)[i] = z1;
}

__global__ void zero_kernel(float* __restrict__ out, long long out_size) {
    int i = blockIdx.x * blockDim.x + threadIdx.x;
    if (i < NB * LL) { g_R[i] = 0.f; g_RM[i] = 0.f; }
    if (i < NB * SS) g_Cs[i] = 0.f;
    long long NLS = (long long)NB * LL * SS;
    long long extras = (long long)3 * NB * LL + NB;
    if (out_size >= NLS + extras && i < extras) out[NLS + i] = 0.f;
}

__global__ void recip_kernel() {
    int i = blockIdx.x * blockDim.x + threadIdx.x;
    if (i < NB * LL) g_iR[i] = __frcp_rn(g_R[i]);
    if (i < NB * SS) g_iC[i] = __frcp_rn(g_Cs[i]);
}

// ---------------- GEMM: e = exp(sim) -> out; accumulate row/col sums ----------------
__global__ void __launch_bounds__(256, 2) gemm_kernel(float* __restrict__ out) {
    __shared__ __half sA[2][TILE * PAD];
    __shared__ __half sB[2][TILE * PAD];
    __shared__ float colsum[TILE];

    const int tid = threadIdx.x, lane = tid & 31, w = tid >> 5;
    const int tn = blockIdx.x, tm = blockIdx.y, nb = blockIdx.z;

    if (tid < TILE) colsum[tid] = 0.f;

    const __half* A = g_h0 + (size_t)nb * LPAD * CC + (size_t)tm * TILE * CC;
    const __half* B = g_h1 + (size_t)nb * LPAD * CC + (size_t)tn * TILE * CC;

    const int v0 = tid, v1 = tid + 256;   // 512 float4 vectors per tile-stage

    auto gaddr = [&](const __half* src, int kc, int v) -> const float4* {
        int row = v >> 2, kv = v & 3;
        return reinterpret_cast<const float4*>(src + (size_t)row * CC + kc * BK + kv * 8);
    };
    auto sput = [&](__half* dst, int v, float4 r) {
        int row = v >> 2, kv = v & 3;
        *reinterpret_cast<float4*>(dst + row * PAD + kv * 8) = r;
    };

    {
        float4 a0 = *gaddr(A, 0, v0), a1 = *gaddr(A, 0, v1);
        float4 b0 = *gaddr(B, 0, v0), b1 = *gaddr(B, 0, v1);
        sput(sA[0], v0, a0); sput(sA[0], v1, a1);
        sput(sB[0], v0, b0); sput(sB[0], v1, b1);
    }
    __syncthreads();

    const int wm = (w & 3) * 32, wn = (w >> 2) * 64;

    float acc[2][8][4];
#pragma unroll
    for (int mt = 0; mt < 2; ++mt)
#pragma unroll
        for (int nt = 0; nt < 8; ++nt)
#pragma unroll
            for (int q = 0; q < 4; ++q) acc[mt][nt][q] = 0.f;

    // precompute ldmatrix shared addresses (per stage)
    uint32_t aBase[2], bBase[2];
    {
        int ar = wm + (lane & 15);
        int ak = (lane >> 4) * 8;
        int i = lane >> 3, r = lane & 7;
        int br = wn + (i >> 1) * 8 + r;
        int bk = (i & 1) * 8;
        for (int s = 0; s < 2; ++s) {
            aBase[s] = sm2u(&sA[s][ar * PAD + ak]);
            bBase[s] = sm2u(&sB[s][br * PAD + bk]);
        }
    }

    for (int kc = 0; kc < NK; ++kc) {
        const int cur = kc & 1, nxt = cur ^ 1;
        float4 a0, a1, b0, b1;
        if (kc + 1 < NK) {
            a0 = *gaddr(A, kc + 1, v0); a1 = *gaddr(A, kc + 1, v1);
            b0 = *gaddr(B, kc + 1, v0); b1 = *gaddr(B, kc + 1, v1);
        }
#pragma unroll
        for (int kk = 0; kk < 2; ++kk) {
            uint32_t af[2][4], bf[4][4];
#pragma unroll
            for (int mt = 0; mt < 2; ++mt)
                ldsm4(af[mt], aBase[cur] + (uint32_t)((mt * 16 * PAD + kk * 16) * 2));
#pragma unroll
            for (int nn = 0; nn < 4; ++nn)
                ldsm4(bf[nn], bBase[cur] + (uint32_t)((nn * 16 * PAD + kk * 16) * 2));
#pragma unroll
            for (int mt = 0; mt < 2; ++mt)
#pragma unroll
                for (int nt = 0; nt < 8; ++nt) {
                    int nn = nt >> 1, sel = (nt & 1) * 2;
                    mma16816(acc[mt][nt], af[mt], bf[nn][sel], bf[nn][sel + 1]);
                }
        }
        if (kc + 1 < NK) {
            sput(sA[nxt], v0, a0); sput(sA[nxt], v1, a1);
            sput(sB[nxt], v0, b0); sput(sB[nxt], v1, b1);
        }
        __syncthreads();
    }

    // ---- epilogue: e = exp(sim); store; row/col sums ----
    const int gID = lane >> 2, tig = lane & 3;
    float rsum[2][2] = {{0.f, 0.f}, {0.f, 0.f}};

#pragma unroll
    for (int nt = 0; nt < 8; ++nt) {
        const int col = tn * TILE + wn + nt * 8 + tig * 2;
        const bool cv = col < SS;  // col,col+1 valid together (both even-aligned)
        float cs0 = 0.f, cs1 = 0.f;
#pragma unroll
        for (int mt = 0; mt < 2; ++mt)
#pragma unroll
            for (int h = 0; h < 2; ++h) {
                const int row = tm * TILE + wm + mt * 16 + h * 8 + gID;
                const bool rvd = row < LL;
                float e0 = cv ? __expf(acc[mt][nt][h * 2 + 0] * SIMSC) : 0.f;
                float e1 = cv ? __expf(acc[mt][nt][h * 2 + 1] * SIMSC) : 0.f;
                rsum[mt][h] += e0 + e1;
                if (rvd) { cs0 += e0; cs1 += e1; }
                if (rvd && cv) {
                    float2 st = make_float2(e0, e1);
                    *reinterpret_cast<float2*>(out + ((size_t)nb * LL + row) * SS + col) = st;
                }
            }
        cs0 += __shfl_xor_sync(0xffffffffu, cs0, 4);
        cs0 += __shfl_xor_sync(0xffffffffu, cs0, 8);
        cs0 += __shfl_xor_sync(0xffffffffu, cs0, 16);
        cs1 += __shfl_xor_sync(0xffffffffu, cs1, 4);
        cs1 += __shfl_xor_sync(0xffffffffu, cs1, 8);
        cs1 += __shfl_xor_sync(0xffffffffu, cs1, 16);
        if (gID == 0) {
            atomicAdd(&colsum[wn + nt * 8 + tig * 2], cs0);
            atomicAdd(&colsum[wn + nt * 8 + tig * 2 + 1], cs1);
        }
    }
#pragma unroll
    for (int mt = 0; mt < 2; ++mt)
#pragma unroll
        for (int h = 0; h < 2; ++h) {
            float r = rsum[mt][h];
            r += __shfl_xor_sync(0xffffffffu, r, 1);
            r += __shfl_xor_sync(0xffffffffu, r, 2);
            const int row = tm * TILE + wm + mt * 16 + h * 8 + gID;
            if (tig == 0 && row < LL) atomicAdd(&g_R[nb * LL + row], r);
        }
    __syncthreads();
    if (tid < TILE) {
        int col = tn * TILE + tid;
        if (col < SS) atomicAdd(&g_Cs[nb * SS + col], colsum[tid]);
    }
}

// ---------------- conf = e*e*invR*invC (in-place), track row max ----------------
__global__ void __launch_bounds__(256) conf_kernel(float* __restrict__ out) {
    const int row = blockIdx.x;            // 0 .. NB*LL-1
    const int nb = row / LL;
    const float ir = g_iR[row];
    float* rowp = out + (size_t)row * SS;
    const float* icp = g_iC + nb * SS;
    float rmax = 0.f;
    for (int c = threadIdx.x * 4; c < SS; c += blockDim.x * 4) {
        float4 e = *reinterpret_cast<const float4*>(rowp + c);
        float4 ic = *reinterpret_cast<const float4*>(icp + c);
        float4 q;
        q.x = e.x * e.x * ir * ic.x;
        q.y = e.y * e.y * ir * ic.y;
        q.z = e.z * e.z * ir * ic.z;
        q.w = e.w * e.w * ir * ic.w;
        *reinterpret_cast<float4*>(rowp + c) = q;
        rmax = fmaxf(fmaxf(rmax, q.x), fmaxf(q.y, fmaxf(q.z, q.w)));
    }
#pragma unroll
    for (int off = 16; off; off >>= 1)
        rmax = fmaxf(rmax, __shfl_xor_sync(0xffffffffu, rmax, off));
    if ((threadIdx.x & 31) == 0)
        atomicMax(reinterpret_cast<int*>(&g_RM[row]), __float_as_int(rmax));
}

// ---------------- match extraction (expected no-op: conf << THR) ----------------
__global__ void match_kernel(float* __restrict__ out, long long out_size) {
    int r = blockIdx.x * blockDim.x + threadIdx.x;
    if (r >= NB * LL) return;
    long long NLS = (long long)NB * LL * SS;
    if (out_size < NLS + (long long)3 * NB * LL + NB) return;
    float rm = g_RM[r];
    if (!(rm > THRV)) return;
    int nb = r / LL;
    const float* crow = out + (size_t)r * SS;
    for (int s = 0; s < SS; ++s) {
        if (crow[s] == rm) {
            bool ismax = true;
            for (int l2 = 0; l2 < LL; ++l2)
                if (out[((size_t)nb * LL + l2) * SS + s] > rm) { ismax = false; break; }
            if (ismax) {
                out[NLS + r] = 1.0f;
                out[NLS + (long long)NB * LL + r] = (float)s;
                out[NLS + (long long)2 * NB * LL + r] = rm;
                atomicAdd(&out[NLS + (long long)3 * NB * LL + nb], 1.0f);
                return;
            }
        }
    }
}

// ---------------- launch ----------------
extern "C" void kernel_launch(void* const* d_in, const int* in_sizes, int n_in,
                              void* d_out, int out_size) {
    const float* f0 = (const float*)d_in[0];
    const float* f1 = (const float*)d_in[1];
    float* out = (float*)d_out;
    long long osz = (long long)out_size;

    long long n4 = (long long)NB * LPAD * CC / 4;
    prep_kernel<<<(unsigned)((n4 + 255) / 256), 256>>>(f0, f1);

    int extras = 3 * NB * LL + NB;               // 28802 — must fully cover!
    int zmax = extras > NB * SS ? extras : NB * SS;
    zero_kernel<<<(zmax + 255) / 256, 256>>>(out, osz);

    dim3 grid(NT, NT, NB);
    gemm_kernel<<<grid, 256>>>(out);

    recip_kernel<<<(NB * SS + 255) / 256, 256>>>();

    conf_kernel<<<NB * LL, 256>>>(out);

    match_kernel<<<(NB * LL + 255) / 256, 256>>>(out, osz);
}

// round 5
// speedup vs baseline: 1.1194x; 1.1194x over previous
#include <cuda_runtime.h>
#include <cuda_fp16.h>
#include <cstdint>

// CoarseMatching: N=2, L=S=4800, C=256
#define NB 2
#define LL 4800
#define SS 4800
#define CC 256
#define TILE 128
#define NT ((LL + TILE - 1) / TILE)   // 38
#define LPAD (NT * TILE)              // 4864 padded rows
#define BK 32
#define NK (CC / BK)                  // 8
#define PAD 40                        // smem row stride in halves (80B)
#define STG_HALVES (TILE * PAD)       // 5120 halves = 10240 B per stage per array
#define STG_BYTES (STG_HALVES * 2)
#define SIMSC 0.0390625f              // (1/256)/0.1
#define THRV 0.2f

// ---------------- device scratch ----------------
__device__ __half g_h0[NB * LPAD * CC];
__device__ __half g_h1[NB * LPAD * CC];
__device__ float  g_R [NB * LL];   // row sums of exp(sim)
__device__ float  g_Cs[NB * SS];   // col sums of exp(sim)
__device__ float  g_iC[NB * SS];   // 1/colsum
__device__ float  g_RM[NB * LL];   // per-row max of conf

// ---------------- PTX helpers ----------------
__device__ __forceinline__ uint32_t sm2u(const void* p) {
    uint32_t a;
    asm("{ .reg .u64 t; cvta.to.shared.u64 t, %1; cvt.u32.u64 %0, t; }" : "=r"(a) : "l"(p));
    return a;
}

__device__ __forceinline__ void ldsm4(uint32_t* r, uint32_t addr) {
    asm volatile("ldmatrix.sync.aligned.m8n8.x4.shared.b16 {%0,%1,%2,%3}, [%4];"
                 : "=r"(r[0]), "=r"(r[1]), "=r"(r[2]), "=r"(r[3]) : "r"(addr));
}

__device__ __forceinline__ void mma16816(float* d, const uint32_t* a, uint32_t b0, uint32_t b1) {
    asm volatile(
        "mma.sync.aligned.m16n8k16.row.col.f32.f16.f16.f32 "
        "{%0,%1,%2,%3}, {%4,%5,%6,%7}, {%8,%9}, {%0,%1,%2,%3};"
        : "+f"(d[0]), "+f"(d[1]), "+f"(d[2]), "+f"(d[3])
        : "r"(a[0]), "r"(a[1]), "r"(a[2]), "r"(a[3]), "r"(b0), "r"(b1));
}

__device__ __forceinline__ void cpa16(uint32_t smem, const void* gmem) {
    asm volatile("cp.async.cg.shared.global [%0], [%1], 16;" :: "r"(smem), "l"(gmem));
}
__device__ __forceinline__ void cpa_commit() {
    asm volatile("cp.async.commit_group;" ::: "memory");
}
#define CPA_WAIT(n) asm volatile("cp.async.wait_group %0;" :: "n"(n) : "memory")

// ---------------- prep: fp32 -> fp16 with zero padding; also zeros accumulators ----------------
__global__ void prep_kernel(const float* __restrict__ f0, const float* __restrict__ f1,
                            float* __restrict__ out, long long out_size) {
    long long i = (long long)blockIdx.x * blockDim.x + threadIdx.x;   // one uint2 (4 halves)
    // zero duties (grid is far larger than all of these)
    if (i < NB * LL) { g_R[i] = 0.f; g_RM[i] = 0.f; }
    if (i < NB * SS) g_Cs[i] = 0.f;
    {
        long long NLS = (long long)NB * LL * SS;
        long long extras = (long long)3 * NB * LL + NB;
        if (out_size >= NLS + extras && i < extras) out[NLS + i] = 0.f;
    }
    long long n4 = (long long)NB * LPAD * CC / 4;
    if (i >= n4) return;
    long long t = i * 4;
    int nb = (int)(t / ((long long)LPAD * CC));
    long long rem = t % ((long long)LPAD * CC);
    int row = (int)(rem / CC), c = (int)(rem % CC);
    uint2 z0 = make_uint2(0u, 0u), z1 = make_uint2(0u, 0u);
    if (row < LL) {
        long long s = ((long long)nb * LL + row) * CC + c;
        float4 a = *reinterpret_cast<const float4*>(f0 + s);
        float4 b = *reinterpret_cast<const float4*>(f1 + s);
        __half2 a01 = __floats2half2_rn(a.x, a.y), a23 = __floats2half2_rn(a.z, a.w);
        __half2 b01 = __floats2half2_rn(b.x, b.y), b23 = __floats2half2_rn(b.z, b.w);
        z0 = make_uint2(*(uint32_t*)&a01, *(uint32_t*)&a23);
        z1 = make_uint2(*(uint32_t*)&b01, *(uint32_t*)&b23);
    }
    reinterpret_cast<uint2*>(g_h0)[i] = z0;
    reinterpret_cast<uint2*>(g_h1)[i] = z1;
}

__global__ void recip_kernel() {
    int i = blockIdx.x * blockDim.x + threadIdx.x;
    if (i < NB * SS) g_iC[i] = __frcp_rn(g_Cs[i]);
}

// ---------------- GEMM: e = exp(sim) -> out; accumulate row/col sums ----------------
__global__ void __launch_bounds__(256, 2) gemm_kernel(float* __restrict__ out) {
    __shared__ __half sA[3][STG_HALVES];
    __shared__ __half sB[3][STG_HALVES];
    __shared__ float colsum[TILE];

    const int tid = threadIdx.x, lane = tid & 31, w = tid >> 5;
    const int tn = blockIdx.x, tm = blockIdx.y, nb = blockIdx.z;

    if (tid < TILE) colsum[tid] = 0.f;

    const __half* A = g_h0 + (size_t)nb * LPAD * CC + (size_t)tm * TILE * CC;
    const __half* B = g_h1 + (size_t)nb * LPAD * CC + (size_t)tn * TILE * CC;

    const uint32_t sAu = sm2u(&sA[0][0]), sBu = sm2u(&sB[0][0]);

    // per-thread load slots: 512 float4 vectors per array-stage, 256 threads -> 2 each
    auto stage_load = [&](int kc, int st) {
#pragma unroll
        for (int h = 0; h < 2; ++h) {
            int v = tid + h * 256;
            int row = v >> 2, kv = v & 3;
            uint32_t soff = (uint32_t)st * STG_BYTES + (uint32_t)((row * PAD + kv * 8) * 2);
            const __half* ga = A + (size_t)row * CC + kc * BK + kv * 8;
            const __half* gb = B + (size_t)row * CC + kc * BK + kv * 8;
            cpa16(sAu + soff, ga);
            cpa16(sBu + soff, gb);
        }
        cpa_commit();
    };

    const int wm = (w & 3) * 32, wn = (w >> 2) * 64;

    float acc[2][8][4];
#pragma unroll
    for (int mt = 0; mt < 2; ++mt)
#pragma unroll
        for (int nt = 0; nt < 8; ++nt)
#pragma unroll
            for (int q = 0; q < 4; ++q) acc[mt][nt][q] = 0.f;

    // precompute ldmatrix shared addresses per stage
    uint32_t aBase[3], bBase[3];
    {
        int ar = wm + (lane & 15);
        int ak = (lane >> 4) * 8;
        int i = lane >> 3, r = lane & 7;
        int br = wn + (i >> 1) * 8 + r;
        int bk = (i & 1) * 8;
#pragma unroll
        for (int s = 0; s < 3; ++s) {
            aBase[s] = sm2u(&sA[s][ar * PAD + ak]);
            bBase[s] = sm2u(&sB[s][br * PAD + bk]);
        }
    }

    stage_load(0, 0);
    stage_load(1, 1);

    for (int kc = 0; kc < NK; ++kc) {
        const int cur = kc % 3;
        CPA_WAIT(1);          // stage kc resident (group kc done; kc+1 may pend)
        __syncthreads();      // everyone sees stage kc; everyone done reading stage kc-1
        if (kc + 2 < NK) stage_load(kc + 2, (kc + 2) % 3);
        else cpa_commit();    // keep group numbering uniform
#pragma unroll
        for (int kk = 0; kk < 2; ++kk) {
            uint32_t af[2][4], bf[4][4];
#pragma unroll
            for (int mt = 0; mt < 2; ++mt)
                ldsm4(af[mt], aBase[cur] + (uint32_t)((mt * 16 * PAD + kk * 16) * 2));
#pragma unroll
            for (int nn = 0; nn < 4; ++nn)
                ldsm4(bf[nn], bBase[cur] + (uint32_t)((nn * 16 * PAD + kk * 16) * 2));
#pragma unroll
            for (int mt = 0; mt < 2; ++mt)
#pragma unroll
                for (int nt = 0; nt < 8; ++nt) {
                    int nn = nt >> 1, sel = (nt & 1) * 2;
                    mma16816(acc[mt][nt], af[mt], bf[nn][sel], bf[nn][sel + 1]);
                }
        }
    }
    CPA_WAIT(0);

    // ---- epilogue: e = exp(sim); store; row/col sums ----
    const int gID = lane >> 2, tig = lane & 3;
    float rsum[2][2] = {{0.f, 0.f}, {0.f, 0.f}};

#pragma unroll
    for (int nt = 0; nt < 8; ++nt) {
        const int col = tn * TILE + wn + nt * 8 + tig * 2;
        const bool cv = col < SS;
        float cs0 = 0.f, cs1 = 0.f;
#pragma unroll
        for (int mt = 0; mt < 2; ++mt)
#pragma unroll
            for (int h = 0; h < 2; ++h) {
                const int row = tm * TILE + wm + mt * 16 + h * 8 + gID;
                const bool rvd = row < LL;
                float e0 = cv ? __expf(acc[mt][nt][h * 2 + 0] * SIMSC) : 0.f;
                float e1 = cv ? __expf(acc[mt][nt][h * 2 + 1] * SIMSC) : 0.f;
                rsum[mt][h] += e0 + e1;
                if (rvd) { cs0 += e0; cs1 += e1; }
                if (rvd && cv) {
                    float2 st = make_float2(e0, e1);
                    *reinterpret_cast<float2*>(out + ((size_t)nb * LL + row) * SS + col) = st;
                }
            }
        cs0 += __shfl_xor_sync(0xffffffffu, cs0, 4);
        cs0 += __shfl_xor_sync(0xffffffffu, cs0, 8);
        cs0 += __shfl_xor_sync(0xffffffffu, cs0, 16);
        cs1 += __shfl_xor_sync(0xffffffffu, cs1, 4);
        cs1 += __shfl_xor_sync(0xffffffffu, cs1, 8);
        cs1 += __shfl_xor_sync(0xffffffffu, cs1, 16);
        if (gID == 0) {
            atomicAdd(&colsum[wn + nt * 8 + tig * 2], cs0);
            atomicAdd(&colsum[wn + nt * 8 + tig * 2 + 1], cs1);
        }
    }
#pragma unroll
    for (int mt = 0; mt < 2; ++mt)
#pragma unroll
        for (int h = 0; h < 2; ++h) {
            float r = rsum[mt][h];
            r += __shfl_xor_sync(0xffffffffu, r, 1);
            r += __shfl_xor_sync(0xffffffffu, r, 2);
            const int row = tm * TILE + wm + mt * 16 + h * 8 + gID;
            if (tig == 0 && row < LL) atomicAdd(&g_R[nb * LL + row], r);
        }
    __syncthreads();
    if (tid < TILE) {
        int col = tn * TILE + tid;
        if (col < SS) atomicAdd(&g_Cs[nb * SS + col], colsum[tid]);
    }
}

// ---------------- conf = e*e*(1/R)*invC (in-place), track row max ----------------
__global__ void __launch_bounds__(256) conf_kernel(float* __restrict__ out) {
    const int row = blockIdx.x;            // 0 .. NB*LL-1
    const int nb = row / LL;
    const float ir = __frcp_rn(g_R[row]);
    float* rowp = out + (size_t)row * SS;
    const float* icp = g_iC + nb * SS;
    float rmax = 0.f;
    for (int c = threadIdx.x * 4; c < SS; c += blockDim.x * 4) {
        float4 e = *reinterpret_cast<const float4*>(rowp + c);
        float4 ic = *reinterpret_cast<const float4*>(icp + c);
        float4 q;
        q.x = e.x * e.x * ir * ic.x;
        q.y = e.y * e.y * ir * ic.y;
        q.z = e.z * e.z * ir * ic.z;
        q.w = e.w * e.w * ir * ic.w;
        *reinterpret_cast<float4*>(rowp + c) = q;
        rmax = fmaxf(fmaxf(rmax, q.x), fmaxf(q.y, fmaxf(q.z, q.w)));
    }
#pragma unroll
    for (int off = 16; off; off >>= 1)
        rmax = fmaxf(rmax, __shfl_xor_sync(0xffffffffu, rmax, off));
    if ((threadIdx.x & 31) == 0)
        atomicMax(reinterpret_cast<int*>(&g_RM[row]), __float_as_int(rmax));
}

// ---------------- match extraction (expected no-op: conf << THR) ----------------
__global__ void match_kernel(float* __restrict__ out, long long out_size) {
    int r = blockIdx.x * blockDim.x + threadIdx.x;
    if (r >= NB * LL) return;
    long long NLS = (long long)NB * LL * SS;
    if (out_size < NLS + (long long)3 * NB * LL + NB) return;
    float rm = g_RM[r];
    if (!(rm > THRV)) return;
    int nb = r / LL;
    const float* crow = out + (size_t)r * SS;
    for (int s = 0; s < SS; ++s) {
        if (crow[s] == rm) {
            bool ismax = true;
            for (int l2 = 0; l2 < LL; ++l2)
                if (out[((size_t)nb * LL + l2) * SS + s] > rm) { ismax = false; break; }
            if (ismax) {
                out[NLS + r] = 1.0f;
                out[NLS + (long long)NB * LL + r] = (float)s;
                out[NLS + (long long)2 * NB * LL + r] = rm;
                atomicAdd(&out[NLS + (long long)3 * NB * LL + nb], 1.0f);
                return;
            }
        }
    }
}

// ---------------- launch ----------------
extern "C" void kernel_launch(void* const* d_in, const int* in_sizes, int n_in,
                              void* d_out, int out_size) {
    const float* f0 = (const float*)d_in[0];
    const float* f1 = (const float*)d_in[1];
    float* out = (float*)d_out;
    long long osz = (long long)out_size;

    long long n4 = (long long)NB * LPAD * CC / 4;
    prep_kernel<<<(unsigned)((n4 + 255) / 256), 256>>>(f0, f1, out, osz);

    dim3 grid(NT, NT, NB);
    gemm_kernel<<<grid, 256>>>(out);

    recip_kernel<<<(NB * SS + 255) / 256, 256>>>();

    conf_kernel<<<NB * LL, 256>>>(out);

    match_kernel<<<(NB * LL + 255) / 256, 256>>>(out, osz);
}